// round 4
// baseline (speedup 1.0000x reference)
#include <cuda_runtime.h>
#include <cstdint>
#include <cstddef>

#define TSIZE (1u << 18)
#define TMASK (TSIZE - 1u)
#define NLEV 16
#define P1 2654435761u
#define P2 805459861u

#define NBUCK 32768   // 32^3 buckets
#define NMAX (1 << 21)

// Device-global scratch (no allocation). 16B alignment for paired LDG.128.
__device__ __align__(16) float2 g_hash[15u * TSIZE];
__device__ __align__(16) float2 g_dense[16 * 16 * 16];
__device__ unsigned g_count[NBUCK];
__device__ unsigned g_cursor[NBUCK];
__device__ float4   g_buf[NMAX];           // bucketed points {x,y,z,idx}

__device__ __forceinline__ int bucket_of(float cx, float cy, float cz) {
    int bx = min(31, max(0, (int)((cx + 1.0f) * 16.0f)));
    int by = min(31, max(0, (int)((cy + 1.0f) * 16.0f)));
    int bz = min(31, max(0, (int)((cz + 1.0f) * 16.0f)));
    return (bx * 32 + by) * 32 + bz;
}

// ---------------------------------------------------------------------------
// Fused: repack tables to float2 + zero histogram + histogram points.
// ---------------------------------------------------------------------------
__global__ void prep_kernel(const float* __restrict__ dense,
                            const float* __restrict__ hash,
                            const float* __restrict__ coords, int N) {
    unsigned i = blockIdx.x * blockDim.x + threadIdx.x;
    if (i < 15u * TSIZE) {
        unsigned l = i >> 18;
        unsigned t = i & TMASK;
        const float* base = hash + (size_t)l * (2u * TSIZE);
        g_hash[i] = make_float2(base[t], base[TSIZE + t]);
    }
    if (i < 4096u)
        g_dense[i] = make_float2(dense[i], dense[4096u + i]);
    if (i < NBUCK)
        g_count[i] = 0u;
}

__global__ void hist_kernel(const float* __restrict__ coords, int N) {
    int i = blockIdx.x * blockDim.x + threadIdx.x;
    if (i >= N) return;
    int b = bucket_of(coords[3 * i], coords[3 * i + 1], coords[3 * i + 2]);
    atomicAdd(&g_count[b], 1u);
}

// Single-block exclusive scan over 32768 counters -> g_cursor.
__global__ __launch_bounds__(1024)
void scan_kernel() {
    __shared__ unsigned part[1024];
    const int t = threadIdx.x;
    const unsigned base = (unsigned)t * 32u;
    unsigned local[32];
    unsigned s = 0;
#pragma unroll
    for (int j = 0; j < 32; ++j) { local[j] = s; s += g_count[base + j]; }
    part[t] = s;
    __syncthreads();
    for (int off = 1; off < 1024; off <<= 1) {
        unsigned v = 0;
        if (t >= off) v = part[t - off];
        __syncthreads();
        if (t >= off) part[t] += v;
        __syncthreads();
    }
    const unsigned pre = (t == 0) ? 0u : part[t - 1];
#pragma unroll
    for (int j = 0; j < 32; ++j) g_cursor[base + j] = pre + local[j];
}

__global__ void scatter_kernel(const float* __restrict__ coords, int N) {
    int i = blockIdx.x * blockDim.x + threadIdx.x;
    if (i >= N) return;
    float x = coords[3 * i], y = coords[3 * i + 1], z = coords[3 * i + 2];
    int b = bucket_of(x, y, z);
    unsigned slot = atomicAdd(&g_cursor[b], 1u);
    g_buf[slot] = make_float4(x, y, z, __int_as_float(i));
}

// ---------------------------------------------------------------------------
// Encode: bucketed order; even-x corner pairs fetched with one LDG.128.
// ---------------------------------------------------------------------------
__global__ __launch_bounds__(256)
void encode_kernel(float* __restrict__ out, int N) {
    int i = blockIdx.x * blockDim.x + threadIdx.x;
    if (i >= N) return;

    const float4 pt = g_buf[i];
    const float cx = pt.x, cy = pt.y, cz = pt.z;
    const int idx = __float_as_int(pt.w);

    float4* __restrict__ out4 = reinterpret_cast<float4*>(out + (size_t)idx * 32);

    constexpr int RES[NLEV] = {16, 20, 25, 32, 40, 50, 64, 80,
                               101, 128, 161, 203, 256, 322, 406, 512};

    float4 obuf = make_float4(0.f, 0.f, 0.f, 0.f);

#pragma unroll
    for (int l = 0; l < NLEV; ++l) {
        const int res = RES[l];
        const float rm1 = (float)(res - 1);

        float px = fminf(fmaxf((cx + 1.0f) * 0.5f * rm1, 0.0f), rm1);
        float py = fminf(fmaxf((cy + 1.0f) * 0.5f * rm1, 0.0f), rm1);
        float pz = fminf(fmaxf((cz + 1.0f) * 0.5f * rm1, 0.0f), rm1);

        int ix0 = (int)px;  float wx = px - (float)ix0;
        int iy0 = (int)py;  float wy = py - (float)iy0;
        int iz0 = (int)pz;  float wz = pz - (float)iz0;
        int ix1 = min(ix0 + 1, res - 1);
        int iy1 = min(iy0 + 1, res - 1);
        int iz1 = min(iz0 + 1, res - 1);

        const float wxv0 = 1.0f - wx, wxv1 = wx;
        const float wyv0 = 1.0f - wy, wyv1 = wy;
        const float wzv0 = 1.0f - wz, wzv1 = wz;

        float a0 = 0.0f, a1 = 0.0f;

        if (l == 0) {
#pragma unroll
            for (int c = 0; c < 8; ++c) {
                const int xi = (c & 4) ? ix1 : ix0;
                const int yi = (c & 2) ? iy1 : iy0;
                const int zi = (c & 1) ? iz1 : iz0;
                const float2 f = __ldg(&g_dense[(xi * 16 + yi) * 16 + zi]);
                const float w = ((c & 4) ? wxv1 : wxv0) *
                                ((c & 2) ? wyv1 : wyv0) *
                                ((c & 1) ? wzv1 : wzv0);
                a0 = fmaf(f.x, w, a0);
                a1 = fmaf(f.y, w, a1);
            }
        } else {
            const float2* __restrict__ tbl = g_hash + (size_t)(l - 1) * TSIZE;
            const unsigned hx0 = (unsigned)ix0;  // prime 1
            const unsigned hx1 = (unsigned)ix1;
            const unsigned hy0 = (unsigned)iy0 * P1;
            const unsigned hy1 = (unsigned)iy1 * P1;
            const unsigned hz0 = (unsigned)iz0 * P2;
            const unsigned hz1 = (unsigned)iz1 * P2;
#pragma unroll
            for (int p = 0; p < 4; ++p) {   // (y,z) combos; x-pair per combo
                const unsigned m = ((p & 2) ? hy1 : hy0) ^ ((p & 1) ? hz1 : hz0);
                const float wyz = ((p & 2) ? wyv1 : wyv0) *
                                  ((p & 1) ? wzv1 : wzv0);
                const unsigned h0 = (hx0 ^ m) & TMASK;
                const unsigned h1 = (hx1 ^ m) & TMASK;
                float2 f0, f1;
                if ((h0 ^ h1) == 1u) {
                    // Adjacent entries (even x): one 16B load covers both.
                    const float4 q = __ldg(reinterpret_cast<const float4*>(
                        tbl + (h0 & ~1u)));
                    if (h0 & 1u) {
                        f0 = make_float2(q.z, q.w);
                        f1 = make_float2(q.x, q.y);
                    } else {
                        f0 = make_float2(q.x, q.y);
                        f1 = make_float2(q.z, q.w);
                    }
                } else {
                    f0 = __ldg(tbl + h0);
                    f1 = __ldg(tbl + h1);
                }
                const float w0 = wxv0 * wyz;
                const float w1 = wxv1 * wyz;
                a0 = fmaf(f0.x, w0, fmaf(f1.x, w1, a0));
                a1 = fmaf(f0.y, w0, fmaf(f1.y, w1, a1));
            }
        }

        if ((l & 1) == 0) {
            obuf.x = a0; obuf.y = a1;
        } else {
            obuf.z = a0; obuf.w = a1;
            out4[l >> 1] = obuf;
        }
    }
}

// ---------------------------------------------------------------------------
// kernel_launch: prep(repack+zero) -> hist -> scan -> scatter -> encode
// ---------------------------------------------------------------------------
extern "C" void kernel_launch(void* const* d_in, const int* in_sizes, int n_in,
                              void* d_out, int out_size) {
    const float* coords = (const float*)d_in[0];
    const float* dense  = (const float*)d_in[1];
    const float* hash   = (const float*)d_in[2];
    float* out = (float*)d_out;

    const int N = in_sizes[0] / 3;
    const int nb = (N + 255) / 256;

    const unsigned prep_total = 15u * TSIZE;
    prep_kernel<<<(prep_total + 255u) / 256u, 256>>>(dense, hash, coords, N);
    hist_kernel<<<nb, 256>>>(coords, N);
    scan_kernel<<<1, 1024>>>();
    scatter_kernel<<<nb, 256>>>(coords, N);
    encode_kernel<<<nb, 256>>>(out, N);
}

// round 5
// speedup vs baseline: 1.0736x; 1.0736x over previous
#include <cuda_runtime.h>
#include <cstdint>
#include <cstddef>

#define TSIZE (1u << 18)
#define TMASK (TSIZE - 1u)
#define NLEV 16
#define P1 2654435761u
#define P2 805459861u

#define NBUCK 32768   // 32^3 buckets
#define NMAX (1 << 21)

// Device-global scratch (no allocation). 16B alignment for paired LDG.128.
__device__ __align__(16) float2 g_hash[15u * TSIZE];
__device__ __align__(16) float2 g_dense[16 * 16 * 16];
__device__ unsigned g_count[NBUCK];
__device__ unsigned g_cursor[NBUCK];
__device__ float4   g_buf[NMAX];           // bucketed points {x,y,z,idx}

__device__ __forceinline__ int bucket_of(float cx, float cy, float cz) {
    int bx = min(31, max(0, (int)((cx + 1.0f) * 16.0f)));
    int by = min(31, max(0, (int)((cy + 1.0f) * 16.0f)));
    int bz = min(31, max(0, (int)((cz + 1.0f) * 16.0f)));
    return (bx * 32 + by) * 32 + bz;
}

// Unconditional 16B gather (address is 16B-aligned -> exactly 1 line/lane).
__device__ __forceinline__ float4 ldg128(const float2* p) {
    float4 q;
    asm("ld.global.nc.v4.f32 {%0,%1,%2,%3}, [%4];"
        : "=f"(q.x), "=f"(q.y), "=f"(q.z), "=f"(q.w) : "l"(p));
    return q;
}

// Predicated 8B gather: loads only when xorv != 1 (no BSSY/BSYNC emitted).
__device__ __forceinline__ void ldg64_if_needed(float2& f, const float2* p,
                                                unsigned xorv) {
    asm("{\n\t"
        ".reg .pred p;\n\t"
        "setp.ne.u32 p, %2, 1;\n\t"
        "@p ld.global.nc.v2.f32 {%0,%1}, [%3];\n\t"
        "}"
        : "+f"(f.x), "+f"(f.y) : "r"(xorv), "l"(p));
}

// ---------------------------------------------------------------------------
// Repack tables to float2 + zero histogram.
// ---------------------------------------------------------------------------
__global__ void prep_kernel(const float* __restrict__ dense,
                            const float* __restrict__ hash) {
    unsigned i = blockIdx.x * blockDim.x + threadIdx.x;
    if (i < 15u * TSIZE) {
        unsigned l = i >> 18;
        unsigned t = i & TMASK;
        const float* base = hash + (size_t)l * (2u * TSIZE);
        g_hash[i] = make_float2(base[t], base[TSIZE + t]);
    }
    if (i < 4096u)
        g_dense[i] = make_float2(dense[i], dense[4096u + i]);
    if (i < NBUCK)
        g_count[i] = 0u;
}

__global__ void hist_kernel(const float* __restrict__ coords, int N) {
    int i = blockIdx.x * blockDim.x + threadIdx.x;
    if (i >= N) return;
    int b = bucket_of(coords[3 * i], coords[3 * i + 1], coords[3 * i + 2]);
    atomicAdd(&g_count[b], 1u);
}

// Single-block exclusive scan over 32768 counters -> g_cursor.
__global__ __launch_bounds__(1024)
void scan_kernel() {
    __shared__ unsigned part[1024];
    const int t = threadIdx.x;
    const unsigned base = (unsigned)t * 32u;
    unsigned local[32];
    unsigned s = 0;
#pragma unroll
    for (int j = 0; j < 32; ++j) { local[j] = s; s += g_count[base + j]; }
    part[t] = s;
    __syncthreads();
    for (int off = 1; off < 1024; off <<= 1) {
        unsigned v = 0;
        if (t >= off) v = part[t - off];
        __syncthreads();
        if (t >= off) part[t] += v;
        __syncthreads();
    }
    const unsigned pre = (t == 0) ? 0u : part[t - 1];
#pragma unroll
    for (int j = 0; j < 32; ++j) g_cursor[base + j] = pre + local[j];
}

__global__ void scatter_kernel(const float* __restrict__ coords, int N) {
    int i = blockIdx.x * blockDim.x + threadIdx.x;
    if (i >= N) return;
    float x = coords[3 * i], y = coords[3 * i + 1], z = coords[3 * i + 2];
    int b = bucket_of(x, y, z);
    unsigned slot = atomicAdd(&g_cursor[b], 1u);
    g_buf[slot] = make_float4(x, y, z, __int_as_float(i));
}

// ---------------------------------------------------------------------------
// Encode: bucketed order; branchless x-pair fetch (LDG.128 + predicated LDG.64).
// ---------------------------------------------------------------------------
__global__ __launch_bounds__(256)
void encode_kernel(float* __restrict__ out, int N) {
    int i = blockIdx.x * blockDim.x + threadIdx.x;
    if (i >= N) return;

    const float4 pt = g_buf[i];
    const float cx = pt.x, cy = pt.y, cz = pt.z;
    const int idx = __float_as_int(pt.w);

    float4* __restrict__ out4 = reinterpret_cast<float4*>(out + (size_t)idx * 32);

    constexpr int RES[NLEV] = {16, 20, 25, 32, 40, 50, 64, 80,
                               101, 128, 161, 203, 256, 322, 406, 512};

    float4 obuf = make_float4(0.f, 0.f, 0.f, 0.f);

#pragma unroll
    for (int l = 0; l < NLEV; ++l) {
        const int res = RES[l];
        const float rm1 = (float)(res - 1);

        float px = fminf(fmaxf((cx + 1.0f) * 0.5f * rm1, 0.0f), rm1);
        float py = fminf(fmaxf((cy + 1.0f) * 0.5f * rm1, 0.0f), rm1);
        float pz = fminf(fmaxf((cz + 1.0f) * 0.5f * rm1, 0.0f), rm1);

        int ix0 = (int)px;  float wx = px - (float)ix0;
        int iy0 = (int)py;  float wy = py - (float)iy0;
        int iz0 = (int)pz;  float wz = pz - (float)iz0;
        int ix1 = min(ix0 + 1, res - 1);
        int iy1 = min(iy0 + 1, res - 1);
        int iz1 = min(iz0 + 1, res - 1);

        const float wxv0 = 1.0f - wx, wxv1 = wx;
        const float wyv0 = 1.0f - wy, wyv1 = wy;
        const float wzv0 = 1.0f - wz, wzv1 = wz;

        float a0 = 0.0f, a1 = 0.0f;

        if (l == 0) {
#pragma unroll
            for (int c = 0; c < 8; ++c) {
                const int xi = (c & 4) ? ix1 : ix0;
                const int yi = (c & 2) ? iy1 : iy0;
                const int zi = (c & 1) ? iz1 : iz0;
                const float2 f = __ldg(&g_dense[(xi * 16 + yi) * 16 + zi]);
                const float w = ((c & 4) ? wxv1 : wxv0) *
                                ((c & 2) ? wyv1 : wyv0) *
                                ((c & 1) ? wzv1 : wzv0);
                a0 = fmaf(f.x, w, a0);
                a1 = fmaf(f.y, w, a1);
            }
        } else {
            const float2* __restrict__ tbl = g_hash + (size_t)(l - 1) * TSIZE;
            const unsigned hx0 = (unsigned)ix0;  // prime 1
            const unsigned hx1 = (unsigned)ix1;
            const unsigned hy0 = (unsigned)iy0 * P1;
            const unsigned hy1 = (unsigned)iy1 * P1;
            const unsigned hz0 = (unsigned)iz0 * P2;
            const unsigned hz1 = (unsigned)iz1 * P2;
#pragma unroll
            for (int p = 0; p < 4; ++p) {   // (y,z) combos; x0/x1 pair per combo
                const unsigned m = ((p & 2) ? hy1 : hy0) ^ ((p & 1) ? hz1 : hz0);
                const float wyz = ((p & 2) ? wyv1 : wyv0) *
                                  ((p & 1) ? wzv1 : wzv0);
                const unsigned h0 = (hx0 ^ m) & TMASK;
                const unsigned h1 = (hx1 ^ m) & TMASK;
                const unsigned xv = h0 ^ h1;          // ==1 -> adjacent pair

                // One 16B load always fetches f0 (and f1 too when xv==1).
                const float4 q = ldg128(tbl + (h0 & ~1u));
                const bool hi = (h0 & 1u);
                const float2 f0 = hi ? make_float2(q.z, q.w)
                                     : make_float2(q.x, q.y);
                float2 f1 = hi ? make_float2(q.x, q.y)
                               : make_float2(q.z, q.w);
                // Predicated fetch of f1 only for non-adjacent lanes.
                ldg64_if_needed(f1, tbl + h1, xv);

                const float w0 = wxv0 * wyz;
                const float w1 = wxv1 * wyz;
                a0 = fmaf(f0.x, w0, a0);
                a1 = fmaf(f0.y, w0, a1);
                a0 = fmaf(f1.x, w1, a0);
                a1 = fmaf(f1.y, w1, a1);
            }
        }

        if ((l & 1) == 0) {
            obuf.x = a0; obuf.y = a1;
        } else {
            obuf.z = a0; obuf.w = a1;
            out4[l >> 1] = obuf;
        }
    }
}

// ---------------------------------------------------------------------------
// kernel_launch: prep -> hist -> scan -> scatter -> encode
// ---------------------------------------------------------------------------
extern "C" void kernel_launch(void* const* d_in, const int* in_sizes, int n_in,
                              void* d_out, int out_size) {
    const float* coords = (const float*)d_in[0];
    const float* dense  = (const float*)d_in[1];
    const float* hash   = (const float*)d_in[2];
    float* out = (float*)d_out;

    const int N = in_sizes[0] / 3;
    const int nb = (N + 255) / 256;

    const unsigned prep_total = 15u * TSIZE;
    prep_kernel<<<(prep_total + 255u) / 256u, 256>>>(dense, hash);
    hist_kernel<<<nb, 256>>>(coords, N);
    scan_kernel<<<1, 1024>>>();
    scatter_kernel<<<nb, 256>>>(coords, N);
    encode_kernel<<<nb, 256>>>(out, N);
}